// round 1
// baseline (speedup 1.0000x reference)
#include <cuda_runtime.h>
#include <math.h>

// ---------------- constants (fixed problem shapes) ----------------
#define B_       4
#define D_       256
#define HC       128
#define WC       128
#define NPIX     (HC * WC)          // 16384
#define RH       64
#define RW       64
#define R_       3
#define S2_      49
#define CIN0     52
#define HID      32
#define SKY      1.6f               // 2048*0.1/128

// corr tile
#define TX       8
#define TY       4
#define HALX     (TX + 2 * R_)      // 14
#define HALY     (TY + 2 * R_)      // 10
#define NVEC     (HALX * HALY)      // 140
#define SMEM_CORR (NVEC * D_ * 4)   // 143360 bytes

// ---------------- scratch (device globals; no allocs allowed) ----------------
__device__ float g_qn[B_ * NPIX * D_];        // normalized, interpolated q  [b][pix][d]
__device__ float g_kn[B_ * NPIX * D_];        // normalized k                [b][pix][d]
__device__ float g_x [B_ * CIN0 * NPIX];      // refine-net input (NCHW)
__device__ float g_h1[B_ * HID * NPIX];
__device__ float g_h2[B_ * HID * NPIX];

// ---------------- helpers ----------------
__device__ __forceinline__ float warpSum(float v) {
#pragma unroll
    for (int m = 16; m; m >>= 1) v += __shfl_xor_sync(0xffffffffu, v, m);
    return v;
}
__device__ __forceinline__ float warpMax(float v) {
#pragma unroll
    for (int m = 16; m; m >>= 1) v = fmaxf(v, __shfl_xor_sync(0xffffffffu, v, m));
    return v;
}

// ---------------- kernel 1: bilinear upsample 64x64 -> 128x128 + L2 norm ----------------
// one warp per output pixel; lane owns 8 channels (two float4 slots)
__global__ void interp_norm_q_kernel(const float* __restrict__ tok, float* __restrict__ qn) {
    int gw = (blockIdx.x * blockDim.x + threadIdx.x) >> 5;
    int l  = threadIdx.x & 31;
    if (gw >= B_ * NPIX) return;
    int b   = gw >> 14;
    int rem = gw & (NPIX - 1);
    int y = rem >> 7, x = rem & 127;

    float sy = y * 0.5f - 0.25f;
    float sx = x * 0.5f - 0.25f;
    int y0 = (int)floorf(sy), x0 = (int)floorf(sx);
    float fy = sy - (float)y0, fx = sx - (float)x0;
    int y0c = min(max(y0, 0), RH - 1), y1c = min(max(y0 + 1, 0), RH - 1);
    int x0c = min(max(x0, 0), RW - 1), x1c = min(max(x0 + 1, 0), RW - 1);
    float w00 = (1.f - fy) * (1.f - fx), w01 = (1.f - fy) * fx;
    float w10 = fy * (1.f - fx),         w11 = fy * fx;

    const float4* t00 = (const float4*)(tok + ((size_t)b * (RH * RW) + y0c * RW + x0c) * D_);
    const float4* t01 = (const float4*)(tok + ((size_t)b * (RH * RW) + y0c * RW + x1c) * D_);
    const float4* t10 = (const float4*)(tok + ((size_t)b * (RH * RW) + y1c * RW + x0c) * D_);
    const float4* t11 = (const float4*)(tok + ((size_t)b * (RH * RW) + y1c * RW + x1c) * D_);

    float4 v[2];
    float ss = 0.f;
#pragma unroll
    for (int j = 0; j < 2; j++) {
        int idx = j * 32 + l;
        float4 a = t00[idx], bb = t01[idx], c = t10[idx], d = t11[idx];
        float4 r;
        r.x = w00 * a.x + w01 * bb.x + w10 * c.x + w11 * d.x;
        r.y = w00 * a.y + w01 * bb.y + w10 * c.y + w11 * d.y;
        r.z = w00 * a.z + w01 * bb.z + w10 * c.z + w11 * d.z;
        r.w = w00 * a.w + w01 * bb.w + w10 * c.w + w11 * d.w;
        ss += r.x * r.x + r.y * r.y + r.z * r.z + r.w * r.w;
        v[j] = r;
    }
    ss = warpSum(ss);
    float inv = 1.f / fmaxf(sqrtf(ss), 1e-12f);
    float4* o = (float4*)(qn + (size_t)gw * D_);
#pragma unroll
    for (int j = 0; j < 2; j++) {
        float4 r = v[j];
        r.x *= inv; r.y *= inv; r.z *= inv; r.w *= inv;
        o[j * 32 + l] = r;
    }
}

// ---------------- kernel 2: L2-normalize vis tokens (already 128x128) ----------------
__global__ void norm_k_kernel(const float* __restrict__ tok, float* __restrict__ kn) {
    int gw = (blockIdx.x * blockDim.x + threadIdx.x) >> 5;
    int l  = threadIdx.x & 31;
    if (gw >= B_ * NPIX) return;
    const float4* src = (const float4*)(tok + (size_t)gw * D_);
    float4 v0 = src[l], v1 = src[32 + l];
    float ss = v0.x * v0.x + v0.y * v0.y + v0.z * v0.z + v0.w * v0.w
             + v1.x * v1.x + v1.y * v1.y + v1.z * v1.z + v1.w * v1.w;
    ss = warpSum(ss);
    float inv = 1.f / fmaxf(sqrtf(ss), 1e-12f);
    float4* o = (float4*)(kn + (size_t)gw * D_);
    v0.x *= inv; v0.y *= inv; v0.z *= inv; v0.w *= inv;
    v1.x *= inv; v1.y *= inv; v1.z *= inv; v1.w *= inv;
    o[l] = v0; o[32 + l] = v1;
}

// ---------------- kernel 3: corr volume + soft-argmax ----------------
// block = 256 thr (8 warps), tile 8x4 pixels, dynamic smem = 14x10 k vectors
__global__ void corr_kernel(const float* __restrict__ qn, const float* __restrict__ kn,
                            const float* __restrict__ log_temp,
                            float* __restrict__ xbuf, float* __restrict__ out) {
    extern __shared__ float ks[];
    float4* ks4 = (float4*)ks;
    int b = blockIdx.z;
    int tX = blockIdx.x, tY = blockIdx.y;
    int tid = threadIdx.x;

    const float4* kn4 = (const float4*)(kn + (size_t)b * NPIX * D_);
    for (int idx = tid; idx < NVEC * (D_ / 4); idx += 256) {
        int vec = idx >> 6, comp = idx & 63;
        int sy = vec / HALX, sx = vec % HALX;
        int gy = min(max(tY * TY + sy - R_, 0), HC - 1);   // replicate pad
        int gx = min(max(tX * TX + sx - R_, 0), WC - 1);
        ks4[idx] = kn4[(size_t)(gy * WC + gx) * (D_ / 4) + comp];
    }
    __syncthreads();

    int w = tid >> 5, l = tid & 31;
    float invT = expf(-log_temp[0]);
    float* xb = xbuf + (size_t)b * CIN0 * NPIX;
    float* ob = out + (size_t)b * 5 * NPIX;

    for (int i = 0; i < 4; i++) {
        int p  = w * 4 + i;
        int py = p >> 3, px = p & 7;
        int gy = tY * TY + py, gx = tX * TX + px;
        const float4* qv = (const float4*)(qn + ((size_t)b * NPIX + gy * WC + gx) * D_);
        float4 q0 = qv[l], q1 = qv[32 + l];

        float c_lo = 0.f, c_hi = 0.f;
#pragma unroll
        for (int o = 0; o < S2_; o++) {
            int oy = o / 7, ox = o % 7;
            int base = ((py + oy) * HALX + (px + ox)) * (D_ / 4);
            float4 k0 = ks4[base + l], k1 = ks4[base + 32 + l];
            float part = q0.x * k0.x + q0.y * k0.y + q0.z * k0.z + q0.w * k0.w
                       + q1.x * k1.x + q1.y * k1.y + q1.z * k1.z + q1.w * k1.w;
            float s = warpSum(part);
            if (l == o)      c_lo = s;
            if (l == o - 32) c_hi = s;
        }

        // softmax over 49 offsets (lane l holds offset l, and l+32 if l<17)
        float l_lo = c_lo * invT;
        float l_hi = (l < 17) ? c_hi * invT : -INFINITY;
        float m = warpMax(fmaxf(l_lo, l_hi));
        float e_lo = expf(l_lo - m);
        float e_hi = (l < 17) ? expf(l_hi - m) : 0.f;
        float ssum = warpSum(e_lo + e_hi);
        float cy_lo = (float)(l / 7 - 3), cx_lo = (float)(l % 7 - 3);
        float cy_hi = (float)((l + 32) / 7 - 3), cx_hi = (float)((l + 32) % 7 - 3);
        float dyv  = warpSum(e_lo * cy_lo + e_hi * cy_hi) / ssum;
        float dxv  = warpSum(e_lo * cx_lo + e_hi * cx_hi) / ssum;
        float conf = warpMax(fmaxf(e_lo, e_hi)) / ssum;

        size_t pix = (size_t)gy * WC + gx;
        xb[(2 + l) * NPIX + pix] = c_lo;
        if (l < 17) xb[(34 + l) * NPIX + pix] = c_hi;
        if (l == 0) {
            xb[pix]             = dyv;
            xb[NPIX + pix]      = dxv;
            xb[51 * NPIX + pix] = conf;
            ob[2 * NPIX + pix]  = dyv;
            ob[3 * NPIX + pix]  = dxv;
            ob[4 * NPIX + pix]  = conf;
        }
    }
}

// ---------------- conv 5x5 SAME (zero pad), 16x16 output tile ----------------
template <int CIN, int COUT, bool DO_GELU>
__global__ void conv5_kernel(const float* __restrict__ in, const float* __restrict__ wgt,
                             const float* __restrict__ bias, float* __restrict__ outp) {
    __shared__ float tile[20 * 20];
    __shared__ float ws[25 * COUT];
    int b  = blockIdx.z;
    int bx = blockIdx.x * 16, by = blockIdx.y * 16;
    int tid = threadIdx.x;
    int tx = tid & 15, ty = tid >> 4;

    float acc[COUT];
#pragma unroll
    for (int co = 0; co < COUT; co++) acc[co] = bias[co];

    for (int ci = 0; ci < CIN; ci++) {
        __syncthreads();
        const float* inp = in + ((size_t)b * CIN + ci) * NPIX;
        for (int idx = tid; idx < 400; idx += 256) {
            int r = idx / 20, c = idx % 20;
            int iy = by + r - 2, ix = bx + c - 2;
            tile[idx] = (iy >= 0 && iy < HC && ix >= 0 && ix < WC) ? inp[iy * WC + ix] : 0.f;
        }
        for (int idx = tid; idx < 25 * COUT; idx += 256) {
            int co = idx / 25, t = idx % 25;
            ws[t * COUT + co] = wgt[((size_t)co * CIN + ci) * 25 + t];
        }
        __syncthreads();
#pragma unroll
        for (int ky = 0; ky < 5; ky++)
#pragma unroll
            for (int kx = 0; kx < 5; kx++) {
                float xv = tile[(ty + ky) * 20 + tx + kx];
                const float* wr = &ws[(ky * 5 + kx) * COUT];
#pragma unroll
                for (int co = 0; co < COUT; co++) acc[co] = fmaf(wr[co], xv, acc[co]);
            }
    }
    size_t pix = (size_t)(by + ty) * WC + (bx + tx);
#pragma unroll
    for (int co = 0; co < COUT; co++) {
        float v = acc[co];
        if (DO_GELU) v = 0.5f * v * (1.f + erff(v * 0.7071067811865476f));
        outp[((size_t)b * COUT + co) * NPIX + pix] = v;
    }
}

// ---------------- final conv 32->2 + residual + sky scaling ----------------
__global__ void conv5_final_kernel(const float* __restrict__ in, const float* __restrict__ wgt,
                                   const float* __restrict__ bias, const float* __restrict__ xbuf,
                                   float* __restrict__ out) {
    __shared__ float tile[20 * 20];
    __shared__ float ws[25 * 2];
    int b  = blockIdx.z;
    int bx = blockIdx.x * 16, by = blockIdx.y * 16;
    int tid = threadIdx.x;
    int tx = tid & 15, ty = tid >> 4;

    float acc0 = bias[0], acc1 = bias[1];
    for (int ci = 0; ci < HID; ci++) {
        __syncthreads();
        const float* inp = in + ((size_t)b * HID + ci) * NPIX;
        for (int idx = tid; idx < 400; idx += 256) {
            int r = idx / 20, c = idx % 20;
            int iy = by + r - 2, ix = bx + c - 2;
            tile[idx] = (iy >= 0 && iy < HC && ix >= 0 && ix < WC) ? inp[iy * WC + ix] : 0.f;
        }
        if (tid < 50) {
            int co = tid / 25, t = tid % 25;
            ws[t * 2 + co] = wgt[((size_t)co * HID + ci) * 25 + t];
        }
        __syncthreads();
#pragma unroll
        for (int t = 0; t < 25; t++) {
            float xv = tile[(ty + t / 5) * 20 + tx + t % 5];
            acc0 = fmaf(ws[t * 2 + 0], xv, acc0);
            acc1 = fmaf(ws[t * 2 + 1], xv, acc1);
        }
    }
    size_t pix = (size_t)(by + ty) * WC + (bx + tx);
    const float* xb = xbuf + (size_t)b * CIN0 * NPIX;
    float rawdy = xb[pix], rawdx = xb[NPIX + pix];
    float* ob = out + (size_t)b * 5 * NPIX;
    ob[pix]        = (rawdx + acc1) * SKY;   // dra  = refined dx * sky
    ob[NPIX + pix] = (rawdy + acc0) * SKY;   // ddec = refined dy * sky
}

// ---------------- launch ----------------
extern "C" void kernel_launch(void* const* d_in, const int* in_sizes, int n_in,
                              void* d_out, int out_size) {
    const float* rubin = (const float*)d_in[0];
    const float* vis   = (const float*)d_in[1];
    const float* w0    = (const float*)d_in[2];
    const float* b0    = (const float*)d_in[3];
    const float* w1    = (const float*)d_in[4];
    const float* b1    = (const float*)d_in[5];
    const float* w2    = (const float*)d_in[6];
    const float* b2    = (const float*)d_in[7];
    const float* logt  = (const float*)d_in[8];
    float* out = (float*)d_out;

    float *qn, *kn, *xb, *h1, *h2;
    cudaGetSymbolAddress((void**)&qn, g_qn);
    cudaGetSymbolAddress((void**)&kn, g_kn);
    cudaGetSymbolAddress((void**)&xb, g_x);
    cudaGetSymbolAddress((void**)&h1, g_h1);
    cudaGetSymbolAddress((void**)&h2, g_h2);

    cudaFuncSetAttribute(corr_kernel, cudaFuncAttributeMaxDynamicSharedMemorySize, SMEM_CORR);

    int nwarps = B_ * NPIX;                 // 65536 warps, 8 per block
    interp_norm_q_kernel<<<nwarps / 8, 256>>>(rubin, qn);
    norm_k_kernel<<<nwarps / 8, 256>>>(vis, kn);
    corr_kernel<<<dim3(WC / TX, HC / TY, B_), 256, SMEM_CORR>>>(qn, kn, logt, xb, out);
    conv5_kernel<CIN0, HID, true><<<dim3(8, 8, B_), 256>>>(xb, w0, b0, h1);
    conv5_kernel<HID,  HID, true><<<dim3(8, 8, B_), 256>>>(h1, w1, b1, h2);
    conv5_final_kernel<<<dim3(8, 8, B_), 256>>>(h2, w2, b2, xb, out);
}

// round 2
// speedup vs baseline: 1.2692x; 1.2692x over previous
#include <cuda_runtime.h>
#include <math.h>

// ---------------- constants (fixed problem shapes) ----------------
#define B_       4
#define D_       256
#define HC       128
#define WC       128
#define NPIX     (HC * WC)          // 16384
#define RH       64
#define RW       64
#define R_       3
#define S2_      49
#define CIN0     52
#define HID      32
#define SKY      1.6f               // 2048*0.1/128

// corr tile
#define TX       8
#define TY       4
#define HALX     (TX + 2 * R_)      // 14
#define HALY     (TY + 2 * R_)      // 10
#define NVEC     (HALX * HALY)      // 140
#define KST      141                // padded vec stride (141 mod 32 = 13, coprime w/ 32)
#define SMEM_CORR ((64 * KST + 8 * 64) * 16)   // ks4 + per-warp q staging = 152576 B

typedef unsigned long long ull;

// ---------------- scratch (device globals; no allocs allowed) ----------------
__device__ float g_qn[B_ * NPIX * D_];        // normalized, interpolated q  [b][pix][d]
__device__ float g_kn[B_ * NPIX * D_];        // normalized k                [b][pix][d]
__device__ float g_x [B_ * CIN0 * NPIX];      // refine-net input (NCHW)
__device__ float g_h1[B_ * HID * NPIX];
__device__ float g_h2[B_ * HID * NPIX];
__device__ float g_wT0[CIN0 * 25 * HID];      // w0 transposed [ci][tap][co]
__device__ float g_wT1[HID * 25 * HID];       // w1 transposed [ci][tap][co]

// ---------------- helpers ----------------
__device__ __forceinline__ float warpSum(float v) {
#pragma unroll
    for (int m = 16; m; m >>= 1) v += __shfl_xor_sync(0xffffffffu, v, m);
    return v;
}
__device__ __forceinline__ float warpMax(float v) {
#pragma unroll
    for (int m = 16; m; m >>= 1) v = fmaxf(v, __shfl_xor_sync(0xffffffffu, v, m));
    return v;
}
__device__ __forceinline__ void fma2(ull& d, ull a, ull b) {
    asm("fma.rn.f32x2 %0, %1, %2, %3;" : "=l"(d) : "l"(a), "l"(b), "l"(d));
}
__device__ __forceinline__ ull pack2(float x, float y) {
    ull r; asm("mov.b64 %0, {%1, %2};" : "=l"(r) : "f"(x), "f"(y)); return r;
}
__device__ __forceinline__ float2 unpack2(ull v) {
    float2 r; asm("mov.b64 {%0, %1}, %2;" : "=f"(r.x), "=f"(r.y) : "l"(v)); return r;
}

// ---------------- kernel 0: transpose weights to [ci][tap][co] ----------------
__global__ void prep_weights_kernel(const float* __restrict__ w0, const float* __restrict__ w1,
                                    float* __restrict__ wT0, float* __restrict__ wT1) {
    int i = blockIdx.x * 256 + threadIdx.x;
    if (i < CIN0 * 25 * HID) {
        int ci = i / (25 * HID), tap = (i / HID) % 25, co = i % HID;
        wT0[i] = w0[((size_t)co * CIN0 + ci) * 25 + tap];
    }
    if (i < HID * 25 * HID) {
        int ci = i / (25 * HID), tap = (i / HID) % 25, co = i % HID;
        wT1[i] = w1[((size_t)co * HID + ci) * 25 + tap];
    }
}

// ---------------- kernel 1: bilinear upsample 64x64 -> 128x128 + L2 norm ----------------
__global__ void interp_norm_q_kernel(const float* __restrict__ tok, float* __restrict__ qn) {
    int gw = (blockIdx.x * blockDim.x + threadIdx.x) >> 5;
    int l  = threadIdx.x & 31;
    if (gw >= B_ * NPIX) return;
    int b   = gw >> 14;
    int rem = gw & (NPIX - 1);
    int y = rem >> 7, x = rem & 127;

    float sy = y * 0.5f - 0.25f;
    float sx = x * 0.5f - 0.25f;
    int y0 = (int)floorf(sy), x0 = (int)floorf(sx);
    float fy = sy - (float)y0, fx = sx - (float)x0;
    int y0c = min(max(y0, 0), RH - 1), y1c = min(max(y0 + 1, 0), RH - 1);
    int x0c = min(max(x0, 0), RW - 1), x1c = min(max(x0 + 1, 0), RW - 1);
    float w00 = (1.f - fy) * (1.f - fx), w01 = (1.f - fy) * fx;
    float w10 = fy * (1.f - fx),         w11 = fy * fx;

    const float4* t00 = (const float4*)(tok + ((size_t)b * (RH * RW) + y0c * RW + x0c) * D_);
    const float4* t01 = (const float4*)(tok + ((size_t)b * (RH * RW) + y0c * RW + x1c) * D_);
    const float4* t10 = (const float4*)(tok + ((size_t)b * (RH * RW) + y1c * RW + x0c) * D_);
    const float4* t11 = (const float4*)(tok + ((size_t)b * (RH * RW) + y1c * RW + x1c) * D_);

    float4 v[2];
    float ss = 0.f;
#pragma unroll
    for (int j = 0; j < 2; j++) {
        int idx = j * 32 + l;
        float4 a = t00[idx], bb = t01[idx], c = t10[idx], d = t11[idx];
        float4 r;
        r.x = w00 * a.x + w01 * bb.x + w10 * c.x + w11 * d.x;
        r.y = w00 * a.y + w01 * bb.y + w10 * c.y + w11 * d.y;
        r.z = w00 * a.z + w01 * bb.z + w10 * c.z + w11 * d.z;
        r.w = w00 * a.w + w01 * bb.w + w10 * c.w + w11 * d.w;
        ss += r.x * r.x + r.y * r.y + r.z * r.z + r.w * r.w;
        v[j] = r;
    }
    ss = warpSum(ss);
    float inv = 1.f / fmaxf(sqrtf(ss), 1e-12f);
    float4* o = (float4*)(qn + (size_t)gw * D_);
#pragma unroll
    for (int j = 0; j < 2; j++) {
        float4 r = v[j];
        r.x *= inv; r.y *= inv; r.z *= inv; r.w *= inv;
        o[j * 32 + l] = r;
    }
}

// ---------------- kernel 2: L2-normalize vis tokens ----------------
__global__ void norm_k_kernel(const float* __restrict__ tok, float* __restrict__ kn) {
    int gw = (blockIdx.x * blockDim.x + threadIdx.x) >> 5;
    int l  = threadIdx.x & 31;
    if (gw >= B_ * NPIX) return;
    const float4* src = (const float4*)(tok + (size_t)gw * D_);
    float4 v0 = src[l], v1 = src[32 + l];
    float ss = v0.x * v0.x + v0.y * v0.y + v0.z * v0.z + v0.w * v0.w
             + v1.x * v1.x + v1.y * v1.y + v1.z * v1.z + v1.w * v1.w;
    ss = warpSum(ss);
    float inv = 1.f / fmaxf(sqrtf(ss), 1e-12f);
    float4* o = (float4*)(kn + (size_t)gw * D_);
    v0.x *= inv; v0.y *= inv; v0.z *= inv; v0.w *= inv;
    v1.x *= inv; v1.y *= inv; v1.z *= inv; v1.w *= inv;
    o[l] = v0; o[32 + l] = v1;
}

// ---------------- kernel 3: corr volume + soft-argmax (lane = offset, f32x2) ----------------
// smem: ks4 [64 dchunk][141 vec] float4, then per-warp q staging [8][64] float4.
__global__ void corr_kernel(const float* __restrict__ qn, const float* __restrict__ kn,
                            const float* __restrict__ log_temp,
                            float* __restrict__ xbuf, float* __restrict__ out) {
    extern __shared__ float4 sm4[];
    float4* ks4 = sm4;               // [dc*KST + vec]
    float4* qsm = sm4 + 64 * KST;    // [warp*64 + dc]
    int b = blockIdx.z;
    int tX = blockIdx.x, tY = blockIdx.y;
    int tid = threadIdx.x;
    int w = tid >> 5, l = tid & 31;

    // load halo of k vectors, transposed to dchunk-major
    const float4* kn4 = (const float4*)(kn + (size_t)b * NPIX * D_);
    for (int v = w; v < NVEC; v += 8) {
        int sy = v / HALX, sx = v % HALX;
        int gy = min(max(tY * TY + sy - R_, 0), HC - 1);
        int gx = min(max(tX * TX + sx - R_, 0), WC - 1);
        const float4* src = kn4 + (size_t)(gy * WC + gx) * (D_ / 4);
        ks4[l * KST + v]        = src[l];
        ks4[(l + 32) * KST + v] = src[32 + l];
    }
    __syncthreads();

    float invT = expf(-log_temp[0]);
    float* xb = xbuf + (size_t)b * CIN0 * NPIX;
    float* ob = out + (size_t)b * 5 * NPIX;

    // per-lane offsets
    int oy_lo = l / 7, ox_lo = l % 7;
    bool hasHi = (l < 17);
    int o2 = hasHi ? l + 32 : l;
    int oy_hi = o2 / 7, ox_hi = o2 % 7;

    for (int i = 0; i < 4; i++) {
        int p  = w * 4 + i;
        int py = p >> 3, px = p & 7;
        int gy = tY * TY + py, gx = tX * TX + px;

        // stage this pixel's q vector into per-warp smem
        const float4* qv = (const float4*)(qn + ((size_t)b * NPIX + gy * WC + gx) * D_);
        qsm[w * 64 + l]      = qv[l];
        qsm[w * 64 + 32 + l] = qv[32 + l];
        __syncwarp();

        int vlo = (py + oy_lo) * HALX + (px + ox_lo);
        int vhi = (py + oy_hi) * HALX + (px + ox_hi);

        ull aL0 = 0, aL1 = 0, aH0 = 0, aH1 = 0;
        const float4* qp = &qsm[w * 64];
#pragma unroll 8
        for (int dc = 0; dc < 64; dc++) {
            ulonglong2 q2 = *(const ulonglong2*)(qp + dc);
            ulonglong2 k2 = *(const ulonglong2*)(ks4 + dc * KST + vlo);
            fma2(aL0, q2.x, k2.x);
            fma2(aL1, q2.y, k2.y);
            if (hasHi) {
                ulonglong2 h2 = *(const ulonglong2*)(ks4 + dc * KST + vhi);
                fma2(aH0, q2.x, h2.x);
                fma2(aH1, q2.y, h2.y);
            }
        }
        float2 s0 = unpack2(aL0), s1 = unpack2(aL1);
        float c_lo = (s0.x + s0.y) + (s1.x + s1.y);
        float2 t0 = unpack2(aH0), t1 = unpack2(aH1);
        float c_hi = (t0.x + t0.y) + (t1.x + t1.y);

        // softmax over 49 offsets (lane l holds offset l, and l+32 if l<17)
        float l_lo = c_lo * invT;
        float l_hi = hasHi ? c_hi * invT : -INFINITY;
        float m = warpMax(fmaxf(l_lo, l_hi));
        float e_lo = expf(l_lo - m);
        float e_hi = hasHi ? expf(l_hi - m) : 0.f;
        float ssum = warpSum(e_lo + e_hi);
        float cy_lo = (float)(oy_lo - 3), cx_lo = (float)(ox_lo - 3);
        float cy_hi = (float)(oy_hi - 3), cx_hi = (float)(ox_hi - 3);
        float dyv  = warpSum(e_lo * cy_lo + e_hi * cy_hi) / ssum;
        float dxv  = warpSum(e_lo * cx_lo + e_hi * cx_hi) / ssum;
        float conf = warpMax(fmaxf(e_lo, e_hi)) / ssum;

        size_t pix = (size_t)gy * WC + gx;
        xb[(2 + l) * NPIX + pix] = c_lo;
        if (hasHi) xb[(34 + l) * NPIX + pix] = c_hi;
        if (l == 0) {
            xb[pix]             = dyv;
            xb[NPIX + pix]      = dxv;
            xb[51 * NPIX + pix] = conf;
            ob[2 * NPIX + pix]  = dyv;
            ob[3 * NPIX + pix]  = dxv;
            ob[4 * NPIX + pix]  = conf;
        }
        __syncwarp();
    }
}

// ---------------- conv 5x5 SAME -> 32 outputs, f32x2 register-blocked ----------------
// block 256 = 16 co-pairs x 16 rows; tile 16x16 outputs; 4 ci per smem stage.
template <int CIN>
__global__ __launch_bounds__(256) void conv5x32_kernel(const float* __restrict__ in,
                                                       const float* __restrict__ wT,
                                                       const float* __restrict__ bias,
                                                       float* __restrict__ outp) {
    __shared__ float tile[4][400];       // [ci][20*20]
    __shared__ float wsm[4 * 25 * 32];   // [ci][tap][co]
    int b  = blockIdx.z;
    int bx = blockIdx.x * 16, by = blockIdx.y * 16;
    int tid = threadIdx.x;
    int c2 = tid & 15;        // co pair index -> co = 2*c2, 2*c2+1
    int pg = tid >> 4;        // output row within tile
    int co0 = 2 * c2;

    ull acc[16];
    ull binit = pack2(bias[co0], bias[co0 + 1]);
#pragma unroll
    for (int p = 0; p < 16; p++) acc[p] = binit;

    for (int s = 0; s < CIN / 4; s++) {
        __syncthreads();
        // stage 4 input-channel tiles (with zero pad)
        for (int idx = tid; idx < 1600; idx += 256) {
            int ci = idx / 400, rem = idx % 400;
            int r = rem / 20, c = rem % 20;
            int iy = by + r - 2, ix = bx + c - 2;
            tile[ci][rem] = (iy >= 0 && iy < HC && ix >= 0 && ix < WC)
                          ? in[((size_t)b * CIN + s * 4 + ci) * NPIX + iy * WC + ix] : 0.f;
        }
        // stage weights (already [ci][tap][co] contiguous)
        for (int idx = tid; idx < 3200; idx += 256)
            wsm[idx] = wT[(size_t)s * 3200 + idx];
        __syncthreads();

        for (int ci = 0; ci < 4; ci++) {
            const float* tci = tile[ci];
            const float* wci = &wsm[ci * 800 + co0];
#pragma unroll
            for (int ky = 0; ky < 5; ky++) {
                const float* row = tci + (pg + ky) * 20;
                float xr[20];
#pragma unroll
                for (int j = 0; j < 5; j++)
                    *(float4*)(xr + 4 * j) = *(const float4*)(row + 4 * j);
                ull xp[20];
#pragma unroll
                for (int j = 0; j < 20; j++) xp[j] = pack2(xr[j], xr[j]);
#pragma unroll
                for (int kx = 0; kx < 5; kx++) {
                    ull w2 = *(const ull*)(wci + (ky * 5 + kx) * 32);
#pragma unroll
                    for (int p = 0; p < 16; p++) fma2(acc[p], w2, xp[p + kx]);
                }
            }
        }
    }

    // epilogue: GELU + store (two co planes, float4 writes)
    float r0[16], r1[16];
#pragma unroll
    for (int p = 0; p < 16; p++) {
        float2 v = unpack2(acc[p]);
        r0[p] = 0.5f * v.x * (1.f + erff(v.x * 0.7071067811865476f));
        r1[p] = 0.5f * v.y * (1.f + erff(v.y * 0.7071067811865476f));
    }
    float* o0 = outp + ((size_t)b * HID + co0) * NPIX + (by + pg) * WC + bx;
    float* o1 = o0 + NPIX;
#pragma unroll
    for (int q = 0; q < 4; q++) {
        *(float4*)(o0 + 4 * q) = make_float4(r0[4 * q], r0[4 * q + 1], r0[4 * q + 2], r0[4 * q + 3]);
        *(float4*)(o1 + 4 * q) = make_float4(r1[4 * q], r1[4 * q + 1], r1[4 * q + 2], r1[4 * q + 3]);
    }
}

// ---------------- final conv 32->2 + residual + sky scaling ----------------
__global__ void conv5_final_kernel(const float* __restrict__ in, const float* __restrict__ wgt,
                                   const float* __restrict__ bias, const float* __restrict__ xbuf,
                                   float* __restrict__ out) {
    __shared__ float tile[20 * 20];
    __shared__ float ws[25 * 2];
    int b  = blockIdx.z;
    int bx = blockIdx.x * 16, by = blockIdx.y * 16;
    int tid = threadIdx.x;
    int tx = tid & 15, ty = tid >> 4;

    float acc0 = bias[0], acc1 = bias[1];
    for (int ci = 0; ci < HID; ci++) {
        __syncthreads();
        const float* inp = in + ((size_t)b * HID + ci) * NPIX;
        for (int idx = tid; idx < 400; idx += 256) {
            int r = idx / 20, c = idx % 20;
            int iy = by + r - 2, ix = bx + c - 2;
            tile[idx] = (iy >= 0 && iy < HC && ix >= 0 && ix < WC) ? inp[iy * WC + ix] : 0.f;
        }
        if (tid < 50) {
            int co = tid / 25, t = tid % 25;
            ws[t * 2 + co] = wgt[((size_t)co * HID + ci) * 25 + t];
        }
        __syncthreads();
#pragma unroll
        for (int t = 0; t < 25; t++) {
            float xv = tile[(ty + t / 5) * 20 + tx + t % 5];
            acc0 = fmaf(ws[t * 2 + 0], xv, acc0);
            acc1 = fmaf(ws[t * 2 + 1], xv, acc1);
        }
    }
    size_t pix = (size_t)(by + ty) * WC + (bx + tx);
    const float* xb = xbuf + (size_t)b * CIN0 * NPIX;
    float rawdy = xb[pix], rawdx = xb[NPIX + pix];
    float* ob = out + (size_t)b * 5 * NPIX;
    ob[pix]        = (rawdx + acc1) * SKY;   // dra  = refined dx * sky
    ob[NPIX + pix] = (rawdy + acc0) * SKY;   // ddec = refined dy * sky
}

// ---------------- launch ----------------
extern "C" void kernel_launch(void* const* d_in, const int* in_sizes, int n_in,
                              void* d_out, int out_size) {
    const float* rubin = (const float*)d_in[0];
    const float* vis   = (const float*)d_in[1];
    const float* w0    = (const float*)d_in[2];
    const float* b0    = (const float*)d_in[3];
    const float* w1    = (const float*)d_in[4];
    const float* b1    = (const float*)d_in[5];
    const float* w2    = (const float*)d_in[6];
    const float* b2    = (const float*)d_in[7];
    const float* logt  = (const float*)d_in[8];
    float* out = (float*)d_out;

    float *qn, *kn, *xb, *h1, *h2, *wT0, *wT1;
    cudaGetSymbolAddress((void**)&qn,  g_qn);
    cudaGetSymbolAddress((void**)&kn,  g_kn);
    cudaGetSymbolAddress((void**)&xb,  g_x);
    cudaGetSymbolAddress((void**)&h1,  g_h1);
    cudaGetSymbolAddress((void**)&h2,  g_h2);
    cudaGetSymbolAddress((void**)&wT0, g_wT0);
    cudaGetSymbolAddress((void**)&wT1, g_wT1);

    cudaFuncSetAttribute(corr_kernel, cudaFuncAttributeMaxDynamicSharedMemorySize, SMEM_CORR);

    prep_weights_kernel<<<(CIN0 * 25 * HID + 255) / 256, 256>>>(w0, w1, wT0, wT1);
    int nwarps = B_ * NPIX;                 // 65536 warps, 8 per block
    interp_norm_q_kernel<<<nwarps / 8, 256>>>(rubin, qn);
    norm_k_kernel<<<nwarps / 8, 256>>>(vis, kn);
    corr_kernel<<<dim3(WC / TX, HC / TY, B_), 256, SMEM_CORR>>>(qn, kn, logt, xb, out);
    conv5x32_kernel<CIN0><<<dim3(8, 8, B_), 256>>>(xb, wT0, b0, h1);
    conv5x32_kernel<HID ><<<dim3(8, 8, B_), 256>>>(h1, wT1, b1, h2);
    conv5_final_kernel<<<dim3(8, 8, B_), 256>>>(h2, w2, b2, xb, out);
}

// round 4
// speedup vs baseline: 1.5830x; 1.2473x over previous
#include <cuda_runtime.h>
#include <math.h>

// ---------------- constants (fixed problem shapes) ----------------
#define B_       4
#define D_       256
#define HC       128
#define WC       128
#define NPIX     (HC * WC)          // 16384
#define RH       64
#define RW       64
#define R_       3
#define S2_      49
#define CIN0     52
#define HID      32
#define SKY      1.6f               // 2048*0.1/128

// corr tile
#define TX       8
#define TY       4
#define HALX     14                 // logical halo width
#define HALY     10
#define NVEC     (HALX * HALY)      // 140
#define SROW     15                 // padded halo row stride (row jump never ==0 mod 8 banks)
#define KST      151                // per-dchunk vec stride (>= 10*15)
#define SMEM_CORR ((64 * KST + 16 * 128) * 16)   // ks4 + per-warp q staging = 187392 B

typedef unsigned long long ull;

// ---------------- scratch (device globals; no allocs allowed) ----------------
__device__ float g_qn[B_ * NPIX * D_];
__device__ float g_kn[B_ * NPIX * D_];
__device__ float g_x [B_ * CIN0 * NPIX];
__device__ float g_h1[B_ * HID * NPIX];
__device__ float g_h2[B_ * HID * NPIX];
__device__ float g_wT0[CIN0 * 25 * HID];
__device__ float g_wT1[HID * 25 * HID];

// ---------------- helpers ----------------
__device__ __forceinline__ float warpSum(float v) {
#pragma unroll
    for (int m = 16; m; m >>= 1) v += __shfl_xor_sync(0xffffffffu, v, m);
    return v;
}
__device__ __forceinline__ float warpMax(float v) {
#pragma unroll
    for (int m = 16; m; m >>= 1) v = fmaxf(v, __shfl_xor_sync(0xffffffffu, v, m));
    return v;
}
__device__ __forceinline__ void fma2(ull& d, ull a, ull b) {
    asm("fma.rn.f32x2 %0, %1, %2, %3;" : "=l"(d) : "l"(a), "l"(b), "l"(d));
}
__device__ __forceinline__ ull pack2(float x, float y) {
    ull r; asm("mov.b64 %0, {%1, %2};" : "=l"(r) : "f"(x), "f"(y)); return r;
}
__device__ __forceinline__ float2 unpack2(ull v) {
    float2 r; asm("mov.b64 {%0, %1}, %2;" : "=f"(r.x), "=f"(r.y) : "l"(v)); return r;
}

// ---------------- kernel 0: transpose weights to [ci][tap][co] ----------------
__global__ void prep_weights_kernel(const float* __restrict__ w0, const float* __restrict__ w1,
                                    float* __restrict__ wT0, float* __restrict__ wT1) {
    int i = blockIdx.x * 256 + threadIdx.x;
    if (i < CIN0 * 25 * HID) {
        int ci = i / (25 * HID), tap = (i / HID) % 25, co = i % HID;
        wT0[i] = w0[((size_t)co * CIN0 + ci) * 25 + tap];
    }
    if (i < HID * 25 * HID) {
        int ci = i / (25 * HID), tap = (i / HID) % 25, co = i % HID;
        wT1[i] = w1[((size_t)co * HID + ci) * 25 + tap];
    }
}

// ---------------- kernel 1: bilinear upsample 64x64 -> 128x128 + L2 norm ----------------
__global__ void interp_norm_q_kernel(const float* __restrict__ tok, float* __restrict__ qn) {
    int gw = (blockIdx.x * blockDim.x + threadIdx.x) >> 5;
    int l  = threadIdx.x & 31;
    if (gw >= B_ * NPIX) return;
    int b   = gw >> 14;
    int rem = gw & (NPIX - 1);
    int y = rem >> 7, x = rem & 127;

    float sy = y * 0.5f - 0.25f;
    float sx = x * 0.5f - 0.25f;
    int y0 = (int)floorf(sy), x0 = (int)floorf(sx);
    float fy = sy - (float)y0, fx = sx - (float)x0;
    int y0c = min(max(y0, 0), RH - 1), y1c = min(max(y0 + 1, 0), RH - 1);
    int x0c = min(max(x0, 0), RW - 1), x1c = min(max(x0 + 1, 0), RW - 1);
    float w00 = (1.f - fy) * (1.f - fx), w01 = (1.f - fy) * fx;
    float w10 = fy * (1.f - fx),         w11 = fy * fx;

    const float4* t00 = (const float4*)(tok + ((size_t)b * (RH * RW) + y0c * RW + x0c) * D_);
    const float4* t01 = (const float4*)(tok + ((size_t)b * (RH * RW) + y0c * RW + x1c) * D_);
    const float4* t10 = (const float4*)(tok + ((size_t)b * (RH * RW) + y1c * RW + x0c) * D_);
    const float4* t11 = (const float4*)(tok + ((size_t)b * (RH * RW) + y1c * RW + x1c) * D_);

    float4 v[2];
    float ss = 0.f;
#pragma unroll
    for (int j = 0; j < 2; j++) {
        int idx = j * 32 + l;
        float4 a = t00[idx], bb = t01[idx], c = t10[idx], d = t11[idx];
        float4 r;
        r.x = w00 * a.x + w01 * bb.x + w10 * c.x + w11 * d.x;
        r.y = w00 * a.y + w01 * bb.y + w10 * c.y + w11 * d.y;
        r.z = w00 * a.z + w01 * bb.z + w10 * c.z + w11 * d.z;
        r.w = w00 * a.w + w01 * bb.w + w10 * c.w + w11 * d.w;
        ss += r.x * r.x + r.y * r.y + r.z * r.z + r.w * r.w;
        v[j] = r;
    }
    ss = warpSum(ss);
    float inv = 1.f / fmaxf(sqrtf(ss), 1e-12f);
    float4* o = (float4*)(qn + (size_t)gw * D_);
#pragma unroll
    for (int j = 0; j < 2; j++) {
        float4 r = v[j];
        r.x *= inv; r.y *= inv; r.z *= inv; r.w *= inv;
        o[j * 32 + l] = r;
    }
}

// ---------------- kernel 2: L2-normalize vis tokens ----------------
__global__ void norm_k_kernel(const float* __restrict__ tok, float* __restrict__ kn) {
    int gw = (blockIdx.x * blockDim.x + threadIdx.x) >> 5;
    int l  = threadIdx.x & 31;
    if (gw >= B_ * NPIX) return;
    const float4* src = (const float4*)(tok + (size_t)gw * D_);
    float4 v0 = src[l], v1 = src[32 + l];
    float ss = v0.x * v0.x + v0.y * v0.y + v0.z * v0.z + v0.w * v0.w
             + v1.x * v1.x + v1.y * v1.y + v1.z * v1.z + v1.w * v1.w;
    ss = warpSum(ss);
    float inv = 1.f / fmaxf(sqrtf(ss), 1e-12f);
    float4* o = (float4*)(kn + (size_t)gw * D_);
    v0.x *= inv; v0.y *= inv; v0.z *= inv; v0.w *= inv;
    v1.x *= inv; v1.y *= inv; v1.z *= inv; v1.w *= inv;
    o[l] = v0; o[32 + l] = v1;
}

// ---------------- kernel 3: corr volume + soft-argmax ----------------
// 512 thr = 16 warps; tile 8x4 pixels; warp handles 2 adjacent pixels in one
// interleaved dc loop (8 independent f32x2 accumulator chains).
__global__ __launch_bounds__(512, 1)
void corr_kernel(const float* __restrict__ qn, const float* __restrict__ kn,
                 const float* __restrict__ log_temp,
                 float* __restrict__ xbuf, float* __restrict__ out) {
    extern __shared__ float4 sm4[];
    float4* ks4 = sm4;               // [dc*KST + (vy*SROW+vx)]
    float4* qsm = sm4 + 64 * KST;    // [warp*128 + pix*64 + dc]
    int b = blockIdx.z;
    int tX = blockIdx.x, tY = blockIdx.y;
    int tid = threadIdx.x;
    int w = tid >> 5, l = tid & 31;

    // load halo of k vectors, transposed to dchunk-major, padded row stride
    const float4* kn4 = (const float4*)(kn + (size_t)b * NPIX * D_);
    for (int v = w; v < NVEC; v += 16) {
        int sy = v / HALX, sx = v % HALX;
        int slot = sy * SROW + sx;
        int gy = min(max(tY * TY + sy - R_, 0), HC - 1);
        int gx = min(max(tX * TX + sx - R_, 0), WC - 1);
        const float4* src = kn4 + (size_t)(gy * WC + gx) * (D_ / 4);
        ks4[l * KST + slot]        = src[l];
        ks4[(l + 32) * KST + slot] = src[32 + l];
    }

    // per-warp pixel pair (same row, adjacent x)
    int p0 = w * 2;
    int py = p0 >> 3, px0 = p0 & 7;           // px0 even, px1 = px0+1
    int gy = tY * TY + py, gx0 = tX * TX + px0;

    // stage both q vectors
    const float4* qv0 = (const float4*)(qn + ((size_t)b * NPIX + gy * WC + gx0) * D_);
    const float4* qv1 = (const float4*)(qn + ((size_t)b * NPIX + gy * WC + gx0 + 1) * D_);
    qsm[w * 128 + l]       = qv0[l];
    qsm[w * 128 + 32 + l]  = qv0[32 + l];
    qsm[w * 128 + 64 + l]  = qv1[l];
    qsm[w * 128 + 96 + l]  = qv1[32 + l];
    __syncthreads();

    float invT = expf(-log_temp[0]);
    float* xb = xbuf + (size_t)b * CIN0 * NPIX;
    float* ob = out + (size_t)b * 5 * NPIX;

    // per-lane offsets
    int oy_lo = l / 7, ox_lo = l % 7;
    bool hasHi = (l < 17);
    int o2 = hasHi ? l + 32 : l;
    int oy_hi = o2 / 7, ox_hi = o2 % 7;

    int vlo = (py + oy_lo) * SROW + (px0 + ox_lo);
    int vhi = (py + oy_hi) * SROW + (px0 + ox_hi);

    ull aL0 = 0, aL1 = 0, bL0 = 0, bL1 = 0;
    ull aH0 = 0, aH1 = 0, bH0 = 0, bH1 = 0;
    const float4* qp0 = &qsm[w * 128];
    const float4* qp1 = &qsm[w * 128 + 64];
#pragma unroll 4
    for (int dc = 0; dc < 64; dc++) {
        ulonglong2 q0 = *(const ulonglong2*)(qp0 + dc);
        ulonglong2 q1 = *(const ulonglong2*)(qp1 + dc);
        ulonglong2 kA = *(const ulonglong2*)(ks4 + dc * KST + vlo);
        ulonglong2 kB = *(const ulonglong2*)(ks4 + dc * KST + vlo + 1);
        fma2(aL0, q0.x, kA.x); fma2(aL1, q0.y, kA.y);
        fma2(bL0, q1.x, kB.x); fma2(bL1, q1.y, kB.y);
        if (hasHi) {
            ulonglong2 kC = *(const ulonglong2*)(ks4 + dc * KST + vhi);
            ulonglong2 kD = *(const ulonglong2*)(ks4 + dc * KST + vhi + 1);
            fma2(aH0, q0.x, kC.x); fma2(aH1, q0.y, kC.y);
            fma2(bH0, q1.x, kD.x); fma2(bH1, q1.y, kD.y);
        }
    }

    float clo[2], chi[2];
    { float2 s0 = unpack2(aL0), s1 = unpack2(aL1); clo[0] = (s0.x + s0.y) + (s1.x + s1.y); }
    { float2 s0 = unpack2(bL0), s1 = unpack2(bL1); clo[1] = (s0.x + s0.y) + (s1.x + s1.y); }
    { float2 s0 = unpack2(aH0), s1 = unpack2(aH1); chi[0] = (s0.x + s0.y) + (s1.x + s1.y); }
    { float2 s0 = unpack2(bH0), s1 = unpack2(bH1); chi[1] = (s0.x + s0.y) + (s1.x + s1.y); }

    float cy_lo = (float)(oy_lo - 3), cx_lo = (float)(ox_lo - 3);
    float cy_hi = (float)(oy_hi - 3), cx_hi = (float)(ox_hi - 3);

#pragma unroll
    for (int i = 0; i < 2; i++) {
        float l_lo = clo[i] * invT;
        float l_hi = hasHi ? chi[i] * invT : -INFINITY;
        float m = warpMax(fmaxf(l_lo, l_hi));
        float e_lo = expf(l_lo - m);
        float e_hi = hasHi ? expf(l_hi - m) : 0.f;
        float ssum = warpSum(e_lo + e_hi);
        float dyv  = warpSum(e_lo * cy_lo + e_hi * cy_hi) / ssum;
        float dxv  = warpSum(e_lo * cx_lo + e_hi * cx_hi) / ssum;
        float conf = warpMax(fmaxf(e_lo, e_hi)) / ssum;

        size_t pix = (size_t)gy * WC + (gx0 + i);
        xb[(2 + l) * NPIX + pix] = clo[i];
        if (hasHi) xb[(34 + l) * NPIX + pix] = chi[i];
        if (l == 0) {
            xb[pix]             = dyv;
            xb[NPIX + pix]      = dxv;
            xb[51 * NPIX + pix] = conf;
            ob[2 * NPIX + pix]  = dyv;
            ob[3 * NPIX + pix]  = dxv;
            ob[4 * NPIX + pix]  = conf;
        }
    }
}

// ---------------- conv 5x5 SAME -> 32 outputs, f32x2 register-blocked ----------------
template <int CIN>
__global__ __launch_bounds__(256) void conv5x32_kernel(const float* __restrict__ in,
                                                       const float* __restrict__ wT,
                                                       const float* __restrict__ bias,
                                                       float* __restrict__ outp) {
    __shared__ float tile[4][400];       // [ci][20*20]
    __shared__ float wsm[4 * 25 * 32];   // [ci][tap][co]
    int b  = blockIdx.z;
    int bx = blockIdx.x * 16, by = blockIdx.y * 16;
    int tid = threadIdx.x;
    int c2 = tid & 15;
    int pg = tid >> 4;
    int co0 = 2 * c2;

    ull acc[16];
    ull binit = pack2(bias[co0], bias[co0 + 1]);
#pragma unroll
    for (int p = 0; p < 16; p++) acc[p] = binit;

    for (int s = 0; s < CIN / 4; s++) {
        __syncthreads();
        for (int idx = tid; idx < 1600; idx += 256) {
            int ci = idx / 400, rem = idx % 400;
            int r = rem / 20, c = rem % 20;
            int iy = by + r - 2, ix = bx + c - 2;
            tile[ci][rem] = (iy >= 0 && iy < HC && ix >= 0 && ix < WC)
                          ? in[((size_t)b * CIN + s * 4 + ci) * NPIX + iy * WC + ix] : 0.f;
        }
        for (int idx = tid; idx < 3200; idx += 256)
            wsm[idx] = wT[(size_t)s * 3200 + idx];
        __syncthreads();

        for (int ci = 0; ci < 4; ci++) {
            const float* tci = tile[ci];
            const float* wci = &wsm[ci * 800 + co0];
#pragma unroll
            for (int ky = 0; ky < 5; ky++) {
                const float* row = tci + (pg + ky) * 20;
                float xr[20];
#pragma unroll
                for (int j = 0; j < 5; j++)
                    *(float4*)(xr + 4 * j) = *(const float4*)(row + 4 * j);
                ull xp[20];
#pragma unroll
                for (int j = 0; j < 20; j++) xp[j] = pack2(xr[j], xr[j]);
#pragma unroll
                for (int kx = 0; kx < 5; kx++) {
                    ull w2 = *(const ull*)(wci + (ky * 5 + kx) * 32);
#pragma unroll
                    for (int p = 0; p < 16; p++) fma2(acc[p], w2, xp[p + kx]);
                }
            }
        }
    }

    float r0[16], r1[16];
#pragma unroll
    for (int p = 0; p < 16; p++) {
        float2 v = unpack2(acc[p]);
        r0[p] = 0.5f * v.x * (1.f + erff(v.x * 0.7071067811865476f));
        r1[p] = 0.5f * v.y * (1.f + erff(v.y * 0.7071067811865476f));
    }
    float* o0 = outp + ((size_t)b * HID + co0) * NPIX + (by + pg) * WC + bx;
    float* o1 = o0 + NPIX;
#pragma unroll
    for (int q = 0; q < 4; q++) {
        *(float4*)(o0 + 4 * q) = make_float4(r0[4 * q], r0[4 * q + 1], r0[4 * q + 2], r0[4 * q + 3]);
        *(float4*)(o1 + 4 * q) = make_float4(r1[4 * q], r1[4 * q + 1], r1[4 * q + 2], r1[4 * q + 3]);
    }
}

// ---------------- final conv 32->2 + residual + sky scaling ----------------
__global__ void conv5_final_kernel(const float* __restrict__ in, const float* __restrict__ wgt,
                                   const float* __restrict__ bias, const float* __restrict__ xbuf,
                                   float* __restrict__ out) {
    __shared__ float tile[20 * 20];
    __shared__ float ws[25 * 2];
    int b  = blockIdx.z;
    int bx = blockIdx.x * 16, by = blockIdx.y * 16;
    int tid = threadIdx.x;
    int tx = tid & 15, ty = tid >> 4;

    float acc0 = bias[0], acc1 = bias[1];
    for (int ci = 0; ci < HID; ci++) {
        __syncthreads();
        const float* inp = in + ((size_t)b * HID + ci) * NPIX;
        for (int idx = tid; idx < 400; idx += 256) {
            int r = idx / 20, c = idx % 20;
            int iy = by + r - 2, ix = bx + c - 2;
            tile[idx] = (iy >= 0 && iy < HC && ix >= 0 && ix < WC) ? inp[iy * WC + ix] : 0.f;
        }
        if (tid < 50) {
            int co = tid / 25, t = tid % 25;
            ws[t * 2 + co] = wgt[((size_t)co * HID + ci) * 25 + t];
        }
        __syncthreads();
#pragma unroll
        for (int t = 0; t < 25; t++) {
            float xv = tile[(ty + t / 5) * 20 + tx + t % 5];
            acc0 = fmaf(ws[t * 2 + 0], xv, acc0);
            acc1 = fmaf(ws[t * 2 + 1], xv, acc1);
        }
    }
    size_t pix = (size_t)(by + ty) * WC + (bx + tx);
    const float* xb = xbuf + (size_t)b * CIN0 * NPIX;
    float rawdy = xb[pix], rawdx = xb[NPIX + pix];
    float* ob = out + (size_t)b * 5 * NPIX;
    ob[pix]        = (rawdx + acc1) * SKY;
    ob[NPIX + pix] = (rawdy + acc0) * SKY;
}

// ---------------- launch ----------------
extern "C" void kernel_launch(void* const* d_in, const int* in_sizes, int n_in,
                              void* d_out, int out_size) {
    const float* rubin = (const float*)d_in[0];
    const float* vis   = (const float*)d_in[1];
    const float* w0    = (const float*)d_in[2];
    const float* b0    = (const float*)d_in[3];
    const float* w1    = (const float*)d_in[4];
    const float* b1    = (const float*)d_in[5];
    const float* w2    = (const float*)d_in[6];
    const float* b2    = (const float*)d_in[7];
    const float* logt  = (const float*)d_in[8];
    float* out = (float*)d_out;

    float *qn, *kn, *xb, *h1, *h2, *wT0, *wT1;
    cudaGetSymbolAddress((void**)&qn,  g_qn);
    cudaGetSymbolAddress((void**)&kn,  g_kn);
    cudaGetSymbolAddress((void**)&xb,  g_x);
    cudaGetSymbolAddress((void**)&h1,  g_h1);
    cudaGetSymbolAddress((void**)&h2,  g_h2);
    cudaGetSymbolAddress((void**)&wT0, g_wT0);
    cudaGetSymbolAddress((void**)&wT1, g_wT1);

    cudaFuncSetAttribute(corr_kernel, cudaFuncAttributeMaxDynamicSharedMemorySize, SMEM_CORR);

    prep_weights_kernel<<<(CIN0 * 25 * HID + 255) / 256, 256>>>(w0, w1, wT0, wT1);
    int nwarps = B_ * NPIX;
    interp_norm_q_kernel<<<nwarps / 8, 256>>>(rubin, qn);
    norm_k_kernel<<<nwarps / 8, 256>>>(vis, kn);
    corr_kernel<<<dim3(WC / TX, HC / TY, B_), 512, SMEM_CORR>>>(qn, kn, logt, xb, out);
    conv5x32_kernel<CIN0><<<dim3(8, 8, B_), 256>>>(xb, wT0, b0, h1);
    conv5x32_kernel<HID ><<<dim3(8, 8, B_), 256>>>(h1, wT1, b1, h2);
    conv5_final_kernel<<<dim3(8, 8, B_), 256>>>(h2, w2, b2, xb, out);
}